// round 2
// baseline (speedup 1.0000x reference)
#include <cuda_runtime.h>
#include <cuda_bf16.h>
#include <cstdint>

#define BB 512
#define DD 256
#define CC_MAX 200000
#define S_SCALE 30.0f
#define MARGIN 0.2f

// -------- device scratch (no allocations allowed) --------
__device__ __nv_bfloat16 g_wn[(size_t)CC_MAX * DD];   // normalized W, bf16
__device__ __nv_bfloat16 g_xn[BB * DD];               // normalized X, bf16
__device__ float g_sumexp[BB];
__device__ float g_cost[BB];
__device__ int   g_targets[BB];

// ---------------------------------------------------------
// prep: detect target dtype (int64 vs int32) + zero accumulators.
// int64 little-endian with values < 2^31 => every odd 32-bit word zero.
__global__ void prep_kernel(const int* __restrict__ t32) {
    __shared__ int flag;
    int i = threadIdx.x;  // 512 threads
    if (i == 0) flag = 0;
    __syncthreads();
    if (i < 256) {
        if (t32[2 * i + 1] != 0) flag = 1;  // racy OR, fine
    }
    __syncthreads();
    int tgt;
    if (flag) {
        tgt = t32[i];                                   // int32 targets
    } else {
        tgt = (int)((const long long*)t32)[i];          // int64 targets
    }
    g_targets[i] = tgt;
    g_sumexp[i] = 0.0f;
}

// ---------------------------------------------------------
// normalize rows of a [nrows x 256] fp32 matrix -> bf16 into g_wn or g_xn.
// Output symbol is resolved in DEVICE code (passing a __device__ array as a
// host-side kernel arg hands the kernel the host shadow address — on GB300
// ATS makes that a silent wrong-memory write).
__global__ void norm_rows_kernel(const float* __restrict__ in, int nrows, int isW) {
    int row = blockIdx.x * 8 + (threadIdx.x >> 5);
    if (row >= nrows) return;
    int lane = threadIdx.x & 31;
    const float4* p = (const float4*)(in + (size_t)row * DD);
    float4 v0 = p[lane];
    float4 v1 = p[lane + 32];
    float s = v0.x * v0.x + v0.y * v0.y + v0.z * v0.z + v0.w * v0.w
            + v1.x * v1.x + v1.y * v1.y + v1.z * v1.z + v1.w * v1.w;
#pragma unroll
    for (int o = 16; o; o >>= 1) s += __shfl_xor_sync(0xffffffffu, s, o);
    float inv = rsqrtf(s);   // s > 0 for gaussian data; eps path unreachable
    __nv_bfloat16* out = isW ? g_wn : g_xn;
    __nv_bfloat162* q = (__nv_bfloat162*)(out + (size_t)row * DD);
    q[2 * lane + 0]        = __floats2bfloat162_rn(v0.x * inv, v0.y * inv);
    q[2 * lane + 1]        = __floats2bfloat162_rn(v0.z * inv, v0.w * inv);
    q[2 * (lane + 32) + 0] = __floats2bfloat162_rn(v1.x * inv, v1.y * inv);
    q[2 * (lane + 32) + 1] = __floats2bfloat162_rn(v1.z * inv, v1.w * inv);
}

// ---------------------------------------------------------
__device__ __forceinline__ float2 bf2_to_f2(unsigned u) {
    __nv_bfloat162 h;
    *reinterpret_cast<unsigned*>(&h) = u;
    return __bfloat1622float2(h);
}

// target cosine: one warp per batch row, dot(xn[b], wn[target[b]])
__global__ void cost_kernel() {
    int b = blockIdx.x * 8 + (threadIdx.x >> 5);   // 64 blocks x 8 warps = 512
    int lane = threadIdx.x & 31;
    int c = g_targets[b];
    const unsigned* xr = (const unsigned*)(g_xn + (size_t)b * DD);
    const unsigned* wr = (const unsigned*)(g_wn + (size_t)c * DD);
    float s = 0.0f;
#pragma unroll
    for (int j = 0; j < 4; j++) {
        float2 fx = bf2_to_f2(xr[lane + 32 * j]);
        float2 fw = bf2_to_f2(wr[lane + 32 * j]);
        s += fx.x * fw.x + fx.y * fw.y;
    }
#pragma unroll
    for (int o = 16; o; o >>= 1) s += __shfl_xor_sync(0xffffffffu, s, o);
    if (lane == 0) g_cost[b] = s;
}

// ---------------------------------------------------------
// fused cosine-GEMM + exp-sum reduction
// CTA: 128-column (class) tile, full K=256 resident; loops 4 m-blocks of 128.
// 8 warps: warp_m in 0..3 (32 rows each), warp_n in 0..1 (64 cols each).
// mma.sync.m16n8k16 bf16 -> fp32.
#define SM_STRIDE 132   // uints per 128-uint row; %4==0 keeps uint4 alignment

__device__ __forceinline__ void mma16816(float* d, const unsigned* a,
                                         unsigned b0, unsigned b1) {
    asm volatile(
        "mma.sync.aligned.m16n8k16.row.col.f32.bf16.bf16.f32 "
        "{%0,%1,%2,%3}, {%4,%5,%6,%7}, {%8,%9}, {%0,%1,%2,%3};\n"
        : "+f"(d[0]), "+f"(d[1]), "+f"(d[2]), "+f"(d[3])
        : "r"(a[0]), "r"(a[1]), "r"(a[2]), "r"(a[3]), "r"(b0), "r"(b1));
}

__global__ void gemm_sumexp_kernel(int C) {
    extern __shared__ unsigned smem[];
    unsigned* ws = smem;                          // 128 * 132 uints
    unsigned* xs = smem + 128 * SM_STRIDE;        // 128 * 132 uints
    float* red = (float*)(smem + 2 * 128 * SM_STRIDE);  // 128 floats

    const int tid = threadIdx.x;
    const int cbase = blockIdx.x * 128;
    const uint4* wptr4 = (const uint4*)g_wn;      // 32 uint4 per row
    const uint4* xptr4 = (const uint4*)g_xn;

    // load W tile (zero-fill beyond C), vectorized 16B
    for (int idx = tid; idx < 128 * 32; idx += 256) {
        int r = idx >> 5, c4 = idx & 31;
        uint4 v = make_uint4(0u, 0u, 0u, 0u);
        int cg = cbase + r;
        if (cg < C) v = wptr4[(size_t)cg * 32 + c4];
        *(uint4*)&ws[r * SM_STRIDE + 4 * c4] = v;
    }

    const int w = tid >> 5, lane = tid & 31;
    const int wm = w & 3, wnn = w >> 2;
    const int g = lane >> 2, t = lane & 3;
    const int m0 = wm * 32, n0 = wnn * 64;

    for (int mb = 0; mb < 4; mb++) {
        __syncthreads();  // W ready (iter 0); xs/red free of prior readers
        for (int idx = tid; idx < 128 * 32; idx += 256) {
            int r = idx >> 5, c4 = idx & 31;
            *(uint4*)&xs[r * SM_STRIDE + 4 * c4] =
                xptr4[(size_t)(mb * 128 + r) * 32 + c4];
        }
        if (tid < 128) red[tid] = 0.0f;
        __syncthreads();

        float acc[2][8][4];
#pragma unroll
        for (int i = 0; i < 2; i++)
#pragma unroll
            for (int j = 0; j < 8; j++)
#pragma unroll
                for (int q = 0; q < 4; q++) acc[i][j][q] = 0.0f;

        for (int k = 0; k < 16; k++) {
            unsigned a[2][4];
#pragma unroll
            for (int i = 0; i < 2; i++) {
                int r = m0 + i * 16 + g;
                const unsigned* base = &xs[r * SM_STRIDE + k * 8 + t];
                a[i][0] = base[0];
                a[i][1] = base[8 * SM_STRIDE];
                a[i][2] = base[4];
                a[i][3] = base[8 * SM_STRIDE + 4];
            }
#pragma unroll
            for (int j = 0; j < 8; j++) {
                int c = n0 + j * 8 + g;
                const unsigned* bb = &ws[c * SM_STRIDE + k * 8 + t];
                unsigned b0 = bb[0], b1 = bb[4];
                mma16816(acc[0][j], a[0], b0, b1);
                mma16816(acc[1][j], a[1], b0, b1);
            }
        }

        // epilogue: exp and reduce over this warp's 16 columns per row
#pragma unroll
        for (int i = 0; i < 2; i++) {
            float s0 = 0.0f, s1 = 0.0f;
#pragma unroll
            for (int j = 0; j < 8; j++) {
                int c0 = cbase + n0 + j * 8 + 2 * t;
                bool v0 = (c0 < C), v1 = (c0 + 1 < C);
                if (v0) {
                    s0 += __expf(S_SCALE * acc[i][j][0] - 30.0f);
                    s1 += __expf(S_SCALE * acc[i][j][2] - 30.0f);
                }
                if (v1) {
                    s0 += __expf(S_SCALE * acc[i][j][1] - 30.0f);
                    s1 += __expf(S_SCALE * acc[i][j][3] - 30.0f);
                }
            }
            atomicAdd(&red[m0 + i * 16 + g], s0);
            atomicAdd(&red[m0 + i * 16 + g + 8], s1);
        }
        __syncthreads();
        if (tid < 128) atomicAdd(&g_sumexp[mb * 128 + tid], red[tid]);
    }
}

// ---------------------------------------------------------
// finalize: margin correction on target term, lse, mean NLL
__global__ void finalize_kernel(float* __restrict__ out) {
    __shared__ double sd[BB];
    int b = threadIdx.x;
    float ct = g_cost[b];
    float lt = S_SCALE * (ct - MARGIN);
    float s = g_sumexp[b] + __expf(lt - 30.0f) - __expf(S_SCALE * ct - 30.0f);
    float nll = 30.0f + logf(s) - lt;
    sd[b] = (double)nll;
    __syncthreads();
    for (int o = 256; o; o >>= 1) {
        if (b < o) sd[b] += sd[b + o];
        __syncthreads();
    }
    if (b == 0) out[0] = (float)(sd[0] / (double)BB);
}

// ---------------------------------------------------------
extern "C" void kernel_launch(void* const* d_in, const int* in_sizes, int n_in,
                              void* d_out, int out_size) {
    const float* inputs  = (const float*)d_in[0];   // [512,256,1]
    const float* weight  = (const float*)d_in[1];   // [C,256,1]
    const int*   targets = (const int*)d_in[2];     // int32 or int64, detected
    float* out = (float*)d_out;

    int C = in_sizes[1] / DD;

    const int smem_bytes = (2 * 128 * SM_STRIDE) * 4 + 128 * 4;
    cudaFuncSetAttribute(gemm_sumexp_kernel,
                         cudaFuncAttributeMaxDynamicSharedMemorySize,
                         smem_bytes);

    prep_kernel<<<1, 512>>>(targets);
    norm_rows_kernel<<<(C + 7) / 8, 256>>>(weight, C, 1);
    norm_rows_kernel<<<BB / 8, 256>>>(inputs, BB, 0);
    cost_kernel<<<BB / 8, 256>>>();
    gemm_sumexp_kernel<<<(C + 127) / 128, 256, smem_bytes>>>(C);
    finalize_kernel<<<1, BB>>>(out);
}

// round 4
// speedup vs baseline: 2.1320x; 2.1320x over previous
#include <cuda_runtime.h>
#include <cuda_bf16.h>
#include <cstdint>

#define BB 512
#define DD 256
#define CC_MAX 200000
#define S_SCALE 30.0f
#define MARGIN 0.2f

// -------- device scratch --------
__device__ __nv_bfloat16 g_wn[(size_t)CC_MAX * DD];   // normalized W, bf16
__device__ __nv_bfloat16 g_xn[BB * DD];               // normalized X, bf16
__device__ float g_sumexp[BB];
__device__ float g_cost[BB];
__device__ int   g_targets[BB];

// ---------------- helpers ----------------
__device__ __forceinline__ uint32_t smem_u32(const void* p) {
    uint32_t a;
    asm("{ .reg .u64 t; cvta.to.shared.u64 t, %1; cvt.u32.u64 %0, t; }"
        : "=r"(a) : "l"(p));
    return a;
}

#define CP16(sa, ga, sz) \
    asm volatile("cp.async.cg.shared.global [%0], [%1], 16, %2;" \
                 :: "r"(sa), "l"(ga), "r"(sz) : "memory")
#define CP16F(sa, ga) \
    asm volatile("cp.async.cg.shared.global [%0], [%1], 16;" \
                 :: "r"(sa), "l"(ga) : "memory")
#define CP_COMMIT() asm volatile("cp.async.commit_group;" ::: "memory")
#define CP_WAIT1()  asm volatile("cp.async.wait_group 1;" ::: "memory")
#define CP_WAIT0()  asm volatile("cp.async.wait_group 0;" ::: "memory")

#define LDSM4(r0, r1, r2, r3, addr) \
    asm volatile("ldmatrix.sync.aligned.m8n8.x4.shared.b16 {%0,%1,%2,%3}, [%4];" \
                 : "=r"(r0), "=r"(r1), "=r"(r2), "=r"(r3) : "r"(addr))

__device__ __forceinline__ void mma16816(float* d, const uint32_t* a,
                                         uint32_t b0, uint32_t b1) {
    asm volatile(
        "mma.sync.aligned.m16n8k16.row.col.f32.bf16.bf16.f32 "
        "{%0,%1,%2,%3}, {%4,%5,%6,%7}, {%8,%9}, {%0,%1,%2,%3};\n"
        : "+f"(d[0]), "+f"(d[1]), "+f"(d[2]), "+f"(d[3])
        : "r"(a[0]), "r"(a[1]), "r"(a[2]), "r"(a[3]), "r"(b0), "r"(b1));
}

// SW128 blocked-atom tile: 128 rows x 256 bf16 (32 chunks of 16B per row).
// Atom = 8 rows x 64 bf16 (1024B); block idx = (r>>3) + (cc>>3)*16.
// Swizzle XOR reduces to ((r&7)<<4) on the chunk-offset bits.
__device__ __forceinline__ uint32_t tile_off(int r, int cc) {
    return (uint32_t)(((r >> 3) + (cc >> 3) * 16) * 1024
                    + (r & 7) * 128 + ((((cc & 7) * 16) ^ ((r & 7) << 4))));
}

// ---------------------------------------------------------
// prep: detect target dtype (int64 vs int32) + zero accumulators.
__global__ void prep_kernel(const int* __restrict__ t32) {
    __shared__ int flag;
    int i = threadIdx.x;  // 512 threads
    if (i == 0) flag = 0;
    __syncthreads();
    if (i < 256) {
        if (t32[2 * i + 1] != 0) flag = 1;
    }
    __syncthreads();
    int tgt = flag ? t32[i] : (int)((const long long*)t32)[i];
    g_targets[i] = tgt;
    g_sumexp[i] = 0.0f;
}

// ---------------------------------------------------------
// normalize rows of a [nrows x 256] fp32 matrix -> bf16 into g_wn or g_xn.
__global__ void norm_rows_kernel(const float* __restrict__ in, int nrows, int isW) {
    int row = blockIdx.x * 8 + (threadIdx.x >> 5);
    if (row >= nrows) return;
    int lane = threadIdx.x & 31;
    const float4* p = (const float4*)(in + (size_t)row * DD);
    float4 v0 = p[lane];
    float4 v1 = p[lane + 32];
    float s = v0.x * v0.x + v0.y * v0.y + v0.z * v0.z + v0.w * v0.w
            + v1.x * v1.x + v1.y * v1.y + v1.z * v1.z + v1.w * v1.w;
#pragma unroll
    for (int o = 16; o; o >>= 1) s += __shfl_xor_sync(0xffffffffu, s, o);
    float inv = rsqrtf(s);
    __nv_bfloat16* out = isW ? g_wn : g_xn;
    __nv_bfloat162* q = (__nv_bfloat162*)(out + (size_t)row * DD);
    q[2 * lane + 0]        = __floats2bfloat162_rn(v0.x * inv, v0.y * inv);
    q[2 * lane + 1]        = __floats2bfloat162_rn(v0.z * inv, v0.w * inv);
    q[2 * (lane + 32) + 0] = __floats2bfloat162_rn(v1.x * inv, v1.y * inv);
    q[2 * (lane + 32) + 1] = __floats2bfloat162_rn(v1.z * inv, v1.w * inv);
}

// ---------------------------------------------------------
__device__ __forceinline__ float2 bf2_to_f2(unsigned u) {
    __nv_bfloat162 h;
    *reinterpret_cast<unsigned*>(&h) = u;
    return __bfloat1622float2(h);
}

__global__ void cost_kernel() {
    int b = blockIdx.x * 8 + (threadIdx.x >> 5);
    int lane = threadIdx.x & 31;
    int c = g_targets[b];
    const unsigned* xr = (const unsigned*)(g_xn + (size_t)b * DD);
    const unsigned* wr = (const unsigned*)(g_wn + (size_t)c * DD);
    float s = 0.0f;
#pragma unroll
    for (int j = 0; j < 4; j++) {
        float2 fx = bf2_to_f2(xr[lane + 32 * j]);
        float2 fw = bf2_to_f2(wr[lane + 32 * j]);
        s += fx.x * fw.x + fx.y * fw.y;
    }
#pragma unroll
    for (int o = 16; o; o >>= 1) s += __shfl_xor_sync(0xffffffffu, s, o);
    if (lane == 0) g_cost[b] = s;
}

// ---------------------------------------------------------
// GEMM + exp-sum: mma.sync m16n8k16 bf16, ldmatrix feeds, cp.async pipeline.
// CTA: 128-class W tile resident; 4 batch blocks of 128, X double-buffered.
#define SM_W   0
#define SM_X0  65536
#define SM_X1  131072
#define SM_TOTAL 196608

__global__ __launch_bounds__(256, 1) void gemm_sumexp_kernel(int C) {
    extern __shared__ char smem[];
    const uint32_t sb = smem_u32(smem);
    const int tid = threadIdx.x, wid = tid >> 5, lane = tid & 31;
    const int cbase = blockIdx.x * 128;

    const char* wsrc = (const char*)g_wn;
    const char* xsrc = (const char*)g_xn;

    // prologue: W tile (zero-fill past C) + X blocks 0,1 async
#pragma unroll
    for (int it = 0; it < 16; it++) {
        int i = tid + 256 * it, r = i >> 5, cc = i & 31;
        int cg = cbase + r;
        int ok = (cg < C);
        const char* ga = wsrc + ((size_t)(ok ? cg : 0) * 32 + cc) * 16;
        CP16(sb + SM_W + tile_off(r, cc), ga, ok ? 16 : 0);
    }
#pragma unroll
    for (int it = 0; it < 16; it++) {
        int i = tid + 256 * it, r = i >> 5, cc = i & 31;
        CP16F(sb + SM_X0 + tile_off(r, cc), xsrc + ((size_t)r * 32 + cc) * 16);
    }
    CP_COMMIT();
#pragma unroll
    for (int it = 0; it < 16; it++) {
        int i = tid + 256 * it, r = i >> 5, cc = i & 31;
        CP16F(sb + SM_X1 + tile_off(r, cc), xsrc + ((size_t)(128 + r) * 32 + cc) * 16);
    }
    CP_COMMIT();
    CP_WAIT1();        // W + X0 resident; X1 in flight
    __syncthreads();

    const int wm = wid & 3, wn = wid >> 2;
    const int m0 = wm * 32, n0 = wn * 64;
    // ldmatrix per-thread addressing components
    const int a_rl   = ((lane >> 3) & 1) * 8 + (lane & 7);
    const int a_cchi = (lane >> 4) & 1;
    const int b_rl   = ((lane >> 4) & 1) * 8 + (lane & 7);
    const int b_cchi = (lane >> 3) & 1;

    for (int b = 0; b < 4; b++) {
        const uint32_t xa = sb + ((b & 1) ? SM_X1 : SM_X0);
        const uint32_t wa = sb + SM_W;

        float acc[2][8][4];
#pragma unroll
        for (int i = 0; i < 2; i++)
#pragma unroll
            for (int j = 0; j < 8; j++)
#pragma unroll
                for (int q = 0; q < 4; q++) acc[i][j][q] = 0.0f;

#pragma unroll
        for (int s = 0; s < 16; s++) {
            uint32_t afr[2][4];
#pragma unroll
            for (int i = 0; i < 2; i++) {
                int r = m0 + 16 * i + a_rl, cc = 2 * s + a_cchi;
                LDSM4(afr[i][0], afr[i][1], afr[i][2], afr[i][3],
                      xa + tile_off(r, cc));
            }
            uint32_t bfr[4][4];
#pragma unroll
            for (int j4 = 0; j4 < 4; j4++) {
                int r = n0 + 16 * j4 + b_rl, cc = 2 * s + b_cchi;
                LDSM4(bfr[j4][0], bfr[j4][1], bfr[j4][2], bfr[j4][3],
                      wa + tile_off(r, cc));
            }
#pragma unroll
            for (int j = 0; j < 8; j++) {
                uint32_t b0 = bfr[j >> 1][(j & 1) * 2];
                uint32_t b1 = bfr[j >> 1][(j & 1) * 2 + 1];
                mma16816(acc[0][j], afr[0], b0, b1);
                mma16816(acc[1][j], afr[1], b0, b1);
            }
        }

        // epilogue: exp + per-row reduce; rows m0 + (lane>>2) + {0,8,16,24}
        float rs[4] = {0.f, 0.f, 0.f, 0.f};
#pragma unroll
        for (int i = 0; i < 2; i++)
#pragma unroll
            for (int j = 0; j < 8; j++) {
                rs[2 * i]     += __expf(fmaf(S_SCALE, acc[i][j][0], -30.f))
                               + __expf(fmaf(S_SCALE, acc[i][j][1], -30.f));
                rs[2 * i + 1] += __expf(fmaf(S_SCALE, acc[i][j][2], -30.f))
                               + __expf(fmaf(S_SCALE, acc[i][j][3], -30.f));
            }
#pragma unroll
        for (int q = 0; q < 4; q++) {
            rs[q] += __shfl_xor_sync(0xffffffffu, rs[q], 1);
            rs[q] += __shfl_xor_sync(0xffffffffu, rs[q], 2);
        }
        if ((lane & 3) == 0) {
            int rbase = b * 128 + m0 + (lane >> 2);
#pragma unroll
            for (int q = 0; q < 4; q++)
                atomicAdd(&g_sumexp[rbase + 8 * q], rs[q]);
        }

        __syncthreads();   // everyone done reading buf[b&1]
        if (b < 2) {
            uint32_t dst = sb + ((b & 1) ? SM_X1 : SM_X0);
#pragma unroll
            for (int it = 0; it < 16; it++) {
                int i = tid + 256 * it, r = i >> 5, cc = i & 31;
                CP16F(dst + tile_off(r, cc),
                      xsrc + ((size_t)((b + 2) * 128 + r) * 32 + cc) * 16);
            }
            CP_COMMIT();
            CP_WAIT1();    // next buffer (issued one group earlier) ready
        } else if (b == 2) {
            CP_WAIT0();    // last buffer ready
        }
        __syncthreads();
    }
}

// ---------------------------------------------------------
// finalize: subtract pad-class contribution, margin correction, lse, mean
__global__ void finalize_kernel(float* __restrict__ out, int npad) {
    __shared__ double sd[BB];
    int b = threadIdx.x;
    float ct = g_cost[b];
    float lt = S_SCALE * (ct - MARGIN);
    float s = g_sumexp[b] - (float)npad * expf(-30.0f)
            + __expf(lt - 30.0f) - __expf(S_SCALE * ct - 30.0f);
    float nll = 30.0f + logf(s) - lt;
    sd[b] = (double)nll;
    __syncthreads();
    for (int o = 256; o; o >>= 1) {
        if (b < o) sd[b] += sd[b + o];
        __syncthreads();
    }
    if (b == 0) out[0] = (float)(sd[0] / (double)BB);
}

// ---------------------------------------------------------
extern "C" void kernel_launch(void* const* d_in, const int* in_sizes, int n_in,
                              void* d_out, int out_size) {
    const float* inputs  = (const float*)d_in[0];
    const float* weight  = (const float*)d_in[1];
    const int*   targets = (const int*)d_in[2];
    float* out = (float*)d_out;

    int C = in_sizes[1] / DD;
    int gridC = (C + 127) / 128;
    int npad = gridC * 128 - C;

    cudaFuncSetAttribute(gemm_sumexp_kernel,
                         cudaFuncAttributeMaxDynamicSharedMemorySize, SM_TOTAL);

    prep_kernel<<<1, 512>>>(targets);
    norm_rows_kernel<<<(C + 7) / 8, 256>>>(weight, C, 1);
    norm_rows_kernel<<<BB / 8, 256>>>(inputs, BB, 0);
    cost_kernel<<<BB / 8, 256>>>();
    gemm_sumexp_kernel<<<gridC, 256, SM_TOTAL>>>(C);
    finalize_kernel<<<1, BB>>>(out, npad);
}